// round 13
// baseline (speedup 1.0000x reference)
#include <cuda_runtime.h>
#include <cstdint>

#define IMGD 128
#define NPIX (IMGD*IMGD)
#define NIMG 40
#define TT 10
#define BB 4
#define HID 512
#define NL 6

// ---------------- scratch (static device globals; no allocation) ----------------
__device__ __align__(16) float g_actf0[(size_t)NIMG * NPIX * 32];    // conv0 out, fp32 NHWC (suspect path)
__device__ float g_buf0[(size_t)NIMG * 128 * NPIX];   // NCHW ping (proven path)
__device__ float g_buf1[(size_t)NIMG * 128 * NPIX];   // NCHW pong
__device__ float g_img[BB * TT * 64];
__device__ float g_h[2][NL][BB][HID];
__device__ float g_c[2][NL][BB][HID];
__device__ float g_h5[TT][BB][HID];

// ---------------- zero initial LSTM state ----------------
__global__ void zero_state_kernel()
{
    int tid = blockIdx.x * blockDim.x + threadIdx.x;
    const int total = NL * BB * HID;
    if (tid < total) {
        ((float*)g_h)[tid] = 0.f;
        ((float*)g_c)[tid] = 0.f;
    }
}

// ---------------- layer0: direct 3->32 conv fp32, emits fp32 NHWC (VERBATIM R10 suspect) ----------------
__global__ void __launch_bounds__(128) conv0_kernel(const float* __restrict__ img,
                                                    const float* __restrict__ w,
                                                    const float* __restrict__ b)
{
    __shared__ float ws[896];
    const int tid = threadIdx.x, y = blockIdx.x, n = blockIdx.y;
    for (int i = tid; i < 896; i += 128) ws[i] = (i < 864) ? w[i] : b[i - 864];
    __syncthreads();
    const int p = tid;
    float x[27];
#pragma unroll
    for (int ic = 0; ic < 3; ++ic)
#pragma unroll
        for (int ky = 0; ky < 3; ++ky)
#pragma unroll
            for (int kx = 0; kx < 3; ++kx) {
                int iy = y + ky - 1, ix = p + kx - 1;
                x[ic * 9 + ky * 3 + kx] = ((unsigned)iy < 128u && (unsigned)ix < 128u)
                    ? img[((size_t)(n * 3 + ic) * 128 + iy) * 128 + ix] : 0.f;
            }
    float* op = g_actf0 + ((size_t)((n * 128 + y) * 128 + p)) * 32;
#pragma unroll 4
    for (int oc = 0; oc < 32; ++oc) {
        float a = ws[864 + oc];
#pragma unroll
        for (int j = 0; j < 27; ++j) a = fmaf(ws[oc * 27 + j], x[j], a);
        op[oc] = fmaxf(a, 0.f);
    }
}

// ---------------- NHWC -> NCHW transpose (g_actf0 -> g_buf0), tiled ----------------
__global__ void __launch_bounds__(256) tr_kernel()
{
    __shared__ float ts[32][33];
    const int n = blockIdx.y;
    const int p0 = blockIdx.x * 32;
    const int tid = threadIdx.x;
    const int c = tid & 31, pr = tid >> 5;
    const float* src = g_actf0 + ((size_t)n * NPIX + p0) * 32;
#pragma unroll
    for (int q = 0; q < 4; ++q)
        ts[c][pr + 8 * q] = src[(pr + 8 * q) * 32 + c];
    __syncthreads();
    const int pw = tid & 31, cw = tid >> 5;
    float* dst = g_buf0 + (size_t)n * 32 * NPIX + p0;
#pragma unroll
    for (int q = 0; q < 4; ++q)
        dst[(cw + 8 * q) * NPIX + pw] = ts[cw + 8 * q][pw];
}

// ---------------- layers 1-3: PROVEN R2 conv8 kernel, VERBATIM (NCHW) ----------------
template<int BM, int THREADS>
__global__ void __launch_bounds__(THREADS)
conv8_kernel(int in_sel, int out_sel,
             const float* __restrict__ wt, const float* __restrict__ bias,
             int IC, int OC)
{
    constexpr int BK = 8, BN = 128, TM = 8, TN = 8;
    constexpr int ASTR = BM + 4, BSTR = BN + 4;
    constexpr int TPR = (THREADS < 128) ? THREADS : 128;
    constexpr int PPT = 128 / TPR;
    constexpr int RPP = THREADS / TPR;
    constexpr int NB  = (BK * BN) / THREADS;

    __shared__ __align__(16) float As[BK * ASTR];
    __shared__ __align__(16) float Bs[BK * BSTR];

    const float* inb = (in_sel == 0) ? g_buf0 : g_buf1;
    float* outb = (out_sel == 0) ? g_buf0 : g_buf1;

    const int n = blockIdx.z;
    const float* in = inb + (size_t)n * IC * NPIX;
    float* out = outb + (size_t)n * OC * NPIX;

    const int y   = blockIdx.x;
    const int oc0 = blockIdx.y * BM;
    const int K   = IC * 9;

    const int tid = threadIdx.x;
    const int tx = tid & 15, ty = tid >> 4;

    const int a_oc = tid >> 1;
    const int a_kq = (tid & 1) * 4;
    const float* aPtr = wt + (size_t)(oc0 + a_oc) * K + a_kq;

    const int jb = tid / TPR;
    const int pb = tid % TPR;

    float4 aReg;
    float  bReg[NB];

    auto loadB = [&](int k0) {
#pragma unroll
        for (int q = 0; q < BK / RPP; ++q) {
            int j  = jb + q * RPP;
            int k  = k0 + j;
            int ic = k / 9;
            int r  = k - ic * 9;
            int ky = r / 3;
            int kx = r - ky * 3;
            int iy = y + ky - 1;
            const float* rowp = in + ic * NPIX + iy * IMGD + kx - 1;
            bool rowok = ((unsigned)iy < 128u);
#pragma unroll
            for (int s = 0; s < PPT; ++s) {
                int pp = pb + s * TPR;
                int ix = pp + kx - 1;
                bReg[q * PPT + s] =
                    (rowok && ((unsigned)ix < 128u)) ? rowp[pp] : 0.f;
            }
        }
    };
    auto storeAB = [&]() {
        As[(a_kq + 0) * ASTR + a_oc] = aReg.x;
        As[(a_kq + 1) * ASTR + a_oc] = aReg.y;
        As[(a_kq + 2) * ASTR + a_oc] = aReg.z;
        As[(a_kq + 3) * ASTR + a_oc] = aReg.w;
#pragma unroll
        for (int q = 0; q < BK / RPP; ++q) {
            int j = jb + q * RPP;
#pragma unroll
            for (int s = 0; s < PPT; ++s) {
                int pp = pb + s * TPR;
                Bs[j * BSTR + pp] = bReg[q * PPT + s];
            }
        }
    };

    aReg = *(const float4*)aPtr;
    loadB(0);
    storeAB();
    __syncthreads();

    float acc[TM][TN];
#pragma unroll
    for (int r = 0; r < TM; ++r)
#pragma unroll
        for (int c = 0; c < TN; ++c) acc[r][c] = 0.f;

    for (int k0 = 0; k0 < K; k0 += BK) {
        const bool more = (k0 + BK) < K;
        if (more) {
            aReg = *(const float4*)(aPtr + k0 + BK);
            loadB(k0 + BK);
        }
#pragma unroll
        for (int j = 0; j < BK; ++j) {
            float4 a0 = *(const float4*)&As[j * ASTR + ty * TM];
            float4 a1 = *(const float4*)&As[j * ASTR + ty * TM + 4];
            float4 b0 = *(const float4*)&Bs[j * BSTR + tx * TN];
            float4 b1 = *(const float4*)&Bs[j * BSTR + tx * TN + 4];
            float av[8] = {a0.x, a0.y, a0.z, a0.w, a1.x, a1.y, a1.z, a1.w};
            float bv[8] = {b0.x, b0.y, b0.z, b0.w, b1.x, b1.y, b1.z, b1.w};
#pragma unroll
            for (int r = 0; r < TM; ++r)
#pragma unroll
                for (int c = 0; c < TN; ++c)
                    acc[r][c] = fmaf(av[r], bv[c], acc[r][c]);
        }
        __syncthreads();
        if (more) {
            storeAB();
            __syncthreads();
        }
    }

#pragma unroll
    for (int r = 0; r < TM; ++r) {
        int oc = oc0 + ty * TM + r;
        float bsv = bias[oc];
        float4 o0, o1;
        o0.x = fmaxf(acc[r][0] + bsv, 0.f);
        o0.y = fmaxf(acc[r][1] + bsv, 0.f);
        o0.z = fmaxf(acc[r][2] + bsv, 0.f);
        o0.w = fmaxf(acc[r][3] + bsv, 0.f);
        o1.x = fmaxf(acc[r][4] + bsv, 0.f);
        o1.y = fmaxf(acc[r][5] + bsv, 0.f);
        o1.z = fmaxf(acc[r][6] + bsv, 0.f);
        o1.w = fmaxf(acc[r][7] + bsv, 0.f);
        float* op = out + (size_t)oc * NPIX + (y << 7) + tx * TN;
        *(float4*)op       = o0;
        *(float4*)(op + 4) = o1;
    }
}

// ---------------- spatial softmax (PROVEN R2, reads g_buf1 NCHW) ----------------
__global__ void ssmax_kernel(int camOff)
{
    const int n = blockIdx.x;
    const int ch = blockIdx.y;
    const float* v = g_buf1 + ((size_t)n * 16 + ch) * NPIX;

    __shared__ float red[256];
    __shared__ float redx[256];
    __shared__ float redy[256];
    const int tid = threadIdx.x;

    float m = -1e30f;
    for (int p = tid; p < NPIX; p += 256) m = fmaxf(m, v[p]);
    red[tid] = m;
    __syncthreads();
    for (int s = 128; s > 0; s >>= 1) {
        if (tid < s) red[tid] = fmaxf(red[tid], red[tid + s]);
        __syncthreads();
    }
    m = red[0];
    __syncthreads();

    float s0 = 0.f, sx = 0.f, sy = 0.f;
    const float sc = 2.f / 127.f;
    for (int p = tid; p < NPIX; p += 256) {
        float e = expf(v[p] - m);
        float xx = (float)(p & 127) * sc - 1.f;
        float yy = (float)(p >> 7) * sc - 1.f;
        s0 += e;
        sx += e * xx;
        sy += e * yy;
    }
    red[tid] = s0; redx[tid] = sx; redy[tid] = sy;
    __syncthreads();
    for (int s = 128; s > 0; s >>= 1) {
        if (tid < s) {
            red[tid]  += red[tid + s];
            redx[tid] += redx[tid + s];
            redy[tid] += redy[tid + s];
        }
        __syncthreads();
    }
    if (tid == 0) {
        g_img[n * 64 + camOff + ch * 2 + 0] = redx[0] / red[0];
        g_img[n * 64 + camOff + ch * 2 + 1] = redy[0] / red[0];
    }
}

// ---------------- LSTM cell (proven) ----------------
__device__ __forceinline__ float sigf(float x) { return 1.f / (1.f + expf(-x)); }

__global__ void lstm_cell_kernel(const float* __restrict__ wih, const float* __restrict__ whh,
                                 const float* __restrict__ bih, const float* __restrict__ bhh,
                                 const float* __restrict__ states, int in_dim, int l, int t,
                                 int writeH5)
{
    __shared__ float xs[BB][576];
    __shared__ float hs[BB][HID];
    const int cur = t & 1, nxt = cur ^ 1;
    const int tid = threadIdx.x;
    const int imoff = in_dim - 64;

    for (int e = tid; e < BB * in_dim; e += blockDim.x) {
        int b = e / in_dim, k = e - b * in_dim;
        float v;
        if (k >= imoff)      v = g_img[(b * TT + t) * 64 + (k - imoff)];
        else if (l == 0)     v = states[(b * TT + t) * 6 + k];
        else                 v = g_h[nxt][l - 1][b][k];
        xs[b][k] = v;
    }
    for (int e = tid; e < BB * HID; e += blockDim.x) {
        int b = e >> 9, k = e & 511;
        hs[b][k] = g_h[cur][l][b][k];
    }
    __syncthreads();

    const int warp = tid >> 5, lane = tid & 31;
    const int u = blockIdx.x * (blockDim.x >> 5) + warp;

    float acc[4][4];
#pragma unroll
    for (int g = 0; g < 4; ++g)
#pragma unroll
        for (int b = 0; b < 4; ++b) acc[g][b] = 0.f;

    for (int k = lane; k < in_dim; k += 32) {
        float x0 = xs[0][k], x1 = xs[1][k], x2 = xs[2][k], x3 = xs[3][k];
#pragma unroll
        for (int g = 0; g < 4; ++g) {
            float w = wih[(u + g * HID) * in_dim + k];
            acc[g][0] += w * x0; acc[g][1] += w * x1;
            acc[g][2] += w * x2; acc[g][3] += w * x3;
        }
    }
    for (int k = lane; k < HID; k += 32) {
        float h0 = hs[0][k], h1 = hs[1][k], h2 = hs[2][k], h3 = hs[3][k];
#pragma unroll
        for (int g = 0; g < 4; ++g) {
            float w = whh[(u + g * HID) * HID + k];
            acc[g][0] += w * h0; acc[g][1] += w * h1;
            acc[g][2] += w * h2; acc[g][3] += w * h3;
        }
    }
#pragma unroll
    for (int off = 16; off; off >>= 1)
#pragma unroll
        for (int g = 0; g < 4; ++g)
#pragma unroll
            for (int b = 0; b < 4; ++b)
                acc[g][b] += __shfl_down_sync(0xffffffffu, acc[g][b], off);

    if (lane == 0) {
        float bi = bih[u]           + bhh[u];
        float bf = bih[u + HID]     + bhh[u + HID];
        float bg = bih[u + 2 * HID] + bhh[u + 2 * HID];
        float bo = bih[u + 3 * HID] + bhh[u + 3 * HID];
#pragma unroll
        for (int b = 0; b < 4; ++b) {
            float gi = sigf(acc[0][b] + bi);
            float gf = sigf(acc[1][b] + bf);
            float gg = tanhf(acc[2][b] + bg);
            float go = sigf(acc[3][b] + bo);
            float c2 = gf * g_c[cur][l][b][u] + gi * gg;
            float h2 = go * tanhf(c2);
            g_c[nxt][l][b][u] = c2;
            g_h[nxt][l][b][u] = h2;
            if (writeH5) g_h5[t][b][u] = h2;
        }
    }
}

// ---------------- final linear head (proven) ----------------
__global__ void outproj_kernel(const float* __restrict__ out_w, const float* __restrict__ out_b,
                               float* __restrict__ out)
{
    const int bt = blockIdx.x;
    const int b = bt / TT, t = bt - b * TT;
    const int warp = threadIdx.x >> 5, lane = threadIdx.x & 31;
    if (warp >= 6) return;
    float acc = 0.f;
    for (int k = lane; k < 576; k += 32) {
        float xv = (k < HID) ? g_h5[t][b][k] : g_img[(b * TT + t) * 64 + (k - HID)];
        acc += xv * out_w[warp * 576 + k];
    }
#pragma unroll
    for (int off = 16; off; off >>= 1) acc += __shfl_down_sync(0xffffffffu, acc, off);
    if (lane == 0) out[(b * TT + t) * 6 + warp] = acc + out_b[warp];
}

// ---------------- launcher ----------------
extern "C" void kernel_launch(void* const* d_in, const int* in_sizes, int n_in,
                              void* d_out, int out_size)
{
    const float* img_m  = (const float*)d_in[0];
    const float* img_s  = (const float*)d_in[1];
    const float* states = (const float*)d_in[2];

    const float* w[2][4];
    const float* bw[2][4];
    for (int c = 0; c < 2; ++c)
        for (int j = 0; j < 4; ++j) {
            w[c][j]  = (const float*)d_in[3 + c * 8 + j * 2];
            bw[c][j] = (const float*)d_in[3 + c * 8 + j * 2 + 1];
        }

    const float* wih0  = (const float*)d_in[19];
    const float* whh0  = (const float*)d_in[20];
    const float* bih0  = (const float*)d_in[21];
    const float* bhh0  = (const float*)d_in[22];
    const float* wih_r = (const float*)d_in[23];
    const float* whh_r = (const float*)d_in[24];
    const float* bih_r = (const float*)d_in[25];
    const float* bhh_r = (const float*)d_in[26];
    const float* out_w = (const float*)d_in[27];
    const float* out_b = (const float*)d_in[28];
    float* out = (float*)d_out;

    zero_state_kernel<<<48, 256>>>();

    for (int c = 0; c < 2; ++c) {
        const float* im = c ? img_s : img_m;
        // SUSPECT path: conv0 NHWC + transpose to NCHW
        conv0_kernel<<<dim3(128, NIMG), 128>>>(im, w[c][0], bw[c][0]);
        tr_kernel<<<dim3(512, NIMG), 256>>>();
        // PROVEN R2 chain: conv8 L1-L3 (NCHW, g_buf0/g_buf1) + ssmax(g_buf1)
        conv8_kernel<64, 128><<<dim3(128, 1, NIMG), 128>>>(0, 1, w[c][1], bw[c][1], 32, 64);
        conv8_kernel<128, 256><<<dim3(128, 1, NIMG), 256>>>(1, 0, w[c][2], bw[c][2], 64, 128);
        conv8_kernel<16, 32><<<dim3(128, 1, NIMG), 32>>>(0, 1, w[c][3], bw[c][3], 128, 16);
        ssmax_kernel<<<dim3(NIMG, 16), 256>>>(c * 32);
    }

    for (int t = 0; t < TT; ++t) {
        lstm_cell_kernel<<<128, 128>>>(wih0, whh0, bih0, bhh0, states, 70, 0, t, 0);
        for (int l = 1; l < NL; ++l) {
            lstm_cell_kernel<<<128, 128>>>(wih_r + (size_t)(l - 1) * 2048 * 576,
                                           whh_r + (size_t)(l - 1) * 2048 * 512,
                                           bih_r + (l - 1) * 2048,
                                           bhh_r + (l - 1) * 2048,
                                           nullptr, 576, l, t, (l == NL - 1) ? 1 : 0);
        }
    }
    outproj_kernel<<<40, 192>>>(out_w, out_b, out);
}

// round 14
// speedup vs baseline: 1.8702x; 1.8702x over previous
#include <cuda_runtime.h>
#include <cuda_fp16.h>
#include <cstdint>

#define IMGD 128
#define NPIX (IMGD*IMGD)
#define NIMG 40
#define TT 10
#define BB 4
#define HID 512
#define NL 6

// ---------------- scratch (static device globals; no allocation) ----------------
__device__ float g_buf0[(size_t)NIMG * 128 * NPIX];   // NCHW ping
__device__ float g_buf1[(size_t)NIMG * 128 * NPIX];   // NCHW pong
__device__ float g_img[BB * TT * 64];
__device__ float g_h[2][NL][BB][HID];
__device__ float g_c[2][NL][BB][HID];
__device__ float g_h5[TT][BB][HID];

// ---------------- helpers ----------------
__device__ __forceinline__ void mma16816(float* d, const uint32_t* a, const uint32_t* b) {
    asm volatile("mma.sync.aligned.m16n8k16.row.col.f32.f16.f16.f32 "
                 "{%0,%1,%2,%3}, {%4,%5,%6,%7}, {%8,%9}, {%0,%1,%2,%3};"
                 : "+f"(d[0]), "+f"(d[1]), "+f"(d[2]), "+f"(d[3])
                 : "r"(a[0]), "r"(a[1]), "r"(a[2]), "r"(a[3]), "r"(b[0]), "r"(b[1]));
}

// ---------------- zero initial LSTM state ----------------
__global__ void zero_state_kernel()
{
    int tid = blockIdx.x * blockDim.x + threadIdx.x;
    const int total = NL * BB * HID;
    if (tid < total) {
        ((float*)g_h)[tid] = 0.f;
        ((float*)g_c)[tid] = 0.f;
    }
}

// ---------------- layer0 (K=27): PROVEN R2 implicit-GEMM kernel, NCHW ----------------
template<int BM, int TM>
__global__ void conv_kernel(const float* __restrict__ ext_in, int out_sel,
                            const float* __restrict__ wt, const float* __restrict__ bias,
                            int IC, int OC)
{
    constexpr int BN = 64, BK = 16, TN = 4;
    constexpr int AST = BM + 4, BST = BN + 4;
    __shared__ __align__(16) float As[BK * AST];
    __shared__ __align__(16) float Bs[BK * BST];

    float* outb = (out_sel == 0) ? g_buf0 : g_buf1;

    const int n = blockIdx.z;
    const float* in = ext_in + (size_t)n * IC * NPIX;
    float* out = outb + (size_t)n * OC * NPIX;

    const int p0  = blockIdx.x * BN;
    const int oc0 = blockIdx.y * BM;
    const int py  = p0 >> 7;
    const int x0  = p0 & 127;
    const int K   = IC * 9;

    const int tid = threadIdx.x;
    const int tx = tid & 15, ty = tid >> 4;

    float acc[TM][TN];
#pragma unroll
    for (int r = 0; r < TM; ++r)
#pragma unroll
        for (int c = 0; c < TN; ++c) acc[r][c] = 0.f;

    for (int k0 = 0; k0 < K; k0 += BK) {
#pragma unroll
        for (int e = tid; e < BM * BK; e += 256) {
            int j = e & (BK - 1);
            int i = e >> 4;
            int k = k0 + j, oc = oc0 + i;
            float v = 0.f;
            if (k < K && oc < OC) v = wt[oc * K + k];
            As[j * AST + i] = v;
        }
#pragma unroll
        for (int e = tid; e < BK * BN; e += 256) {
            int j  = e >> 6;
            int pp = e & 63;
            int k = k0 + j;
            float v = 0.f;
            if (k < K) {
                int ic = k / 9;
                int r  = k - ic * 9;
                int ky = r / 3;
                int kx = r - ky * 3;
                int iy = py + ky - 1;
                int ix = x0 + pp + kx - 1;
                if ((unsigned)iy < 128u && (unsigned)ix < 128u)
                    v = in[ic * NPIX + iy * IMGD + ix];
            }
            Bs[j * BST + pp] = v;
        }
        __syncthreads();

#pragma unroll
        for (int j = 0; j < BK; ++j) {
            float bv[TN];
            float4 b4 = *(const float4*)&Bs[j * BST + tx * TN];
            bv[0] = b4.x; bv[1] = b4.y; bv[2] = b4.z; bv[3] = b4.w;
            float av[TM];
#pragma unroll
            for (int r = 0; r < TM; ++r) av[r] = As[j * AST + ty * TM + r];
#pragma unroll
            for (int r = 0; r < TM; ++r)
#pragma unroll
                for (int c = 0; c < TN; ++c)
                    acc[r][c] = fmaf(av[r], bv[c], acc[r][c]);
        }
        __syncthreads();
    }

#pragma unroll
    for (int r = 0; r < TM; ++r) {
        int oc = oc0 + ty * TM + r;
        if (oc < OC) {
            float bsv = bias[oc];
            float4 o;
            o.x = fmaxf(acc[r][0] + bsv, 0.f);
            o.y = fmaxf(acc[r][1] + bsv, 0.f);
            o.z = fmaxf(acc[r][2] + bsv, 0.f);
            o.w = fmaxf(acc[r][3] + bsv, 0.f);
            *(float4*)&out[oc * NPIX + p0 + tx * TN] = o;
        }
    }
}

// ---------------- layers 1-3: fp16-split mma conv, ZERO-cleverness staging ----------------
// block = (row y, image n), 256 threads (8 warps, 16 pixels each). NCHW in/out.
// K flattened k = ic*9 + ky*3 + kx, chunks of 16, guarded per-element loads
// exactly like the proven conv8 loadB decomposition.
template<int IC, int OC>
__global__ void __launch_bounds__(256)
convmma2_kernel(int in_sel, int out_sel,
                const float* __restrict__ wt, const float* __restrict__ bias)
{
    constexpr int K  = IC * 9;
    constexpr int NT = OC / 8;            // n8 tiles
    constexpr int AP = 128 * 48;          // A plane bytes
    constexpr int BP = OC * 48;           // B plane bytes

    extern __shared__ __align__(16) char sm[];
    char* Ah = sm;
    char* Al = sm + AP;
    char* Bh = sm + 2 * AP;
    char* Bl = Bh + BP;

    const float* inb = (in_sel == 0) ? g_buf0 : g_buf1;
    float* outb = (out_sel == 0) ? g_buf0 : g_buf1;
    const int n = blockIdx.y, y = blockIdx.x;
    const float* in = inb + (size_t)n * IC * NPIX;
    float* out = outb + (size_t)n * OC * NPIX;

    const int tid = threadIdx.x, lane = tid & 31, wid = tid >> 5;
    const int tig = lane & 3, gid = lane >> 2;
    const int R = wid * 16;
    const int pA = tid & 127;       // pixel for A staging
    const int jh = tid >> 7;        // 0/1: which j of the pair

    float acc[NT][4];
#pragma unroll
    for (int t = 0; t < NT; ++t)
#pragma unroll
        for (int i = 0; i < 4; ++i) acc[t][i] = 0.f;

    for (int k0 = 0; k0 < K; k0 += 16) {
        __syncthreads();
        // ---- stage A: 128 pixels x 16 k-values, hi/lo fp16 planes ----
#pragma unroll
        for (int pass = 0; pass < 8; ++pass) {
            int j = pass * 2 + jh;
            int k = k0 + j;
            int ic = k / 9;
            int r  = k - ic * 9;
            int ky = r / 3;
            int kx = r - ky * 3;
            int iy = y + ky - 1;
            int ix = pA + kx - 1;
            float v = ((unsigned)iy < 128u && (unsigned)ix < 128u)
                        ? in[ic * NPIX + iy * IMGD + ix] : 0.f;
            __half h = __float2half_rn(v);
            __half l = __float2half_rn(v - __half2float(h));
            *(unsigned short*)(Ah + pA * 48 + j * 2) = __half_as_ushort(h);
            *(unsigned short*)(Al + pA * 48 + j * 2) = __half_as_ushort(l);
        }
        // ---- stage B: OC x 16 k-values from raw OIHW weights ----
        for (int idx = tid; idx < OC * 16; idx += 256) {
            int oc = idx >> 4, j = idx & 15;
            float v = wt[(size_t)oc * K + k0 + j];
            __half h = __float2half_rn(v);
            __half l = __float2half_rn(v - __half2float(h));
            *(unsigned short*)(Bh + oc * 48 + j * 2) = __half_as_ushort(h);
            *(unsigned short*)(Bl + oc * 48 + j * 2) = __half_as_ushort(l);
        }
        __syncthreads();
        // ---- fragments (PTX ISA tables) + mma ----
        const char* ar0 = Ah + (R + gid) * 48 + tig * 4;
        const char* ar1 = ar0 + 8 * 48;
        uint32_t ah[4], al[4];
        ah[0] = *(const uint32_t*)(ar0);
        ah[1] = *(const uint32_t*)(ar1);
        ah[2] = *(const uint32_t*)(ar0 + 16);
        ah[3] = *(const uint32_t*)(ar1 + 16);
        al[0] = *(const uint32_t*)(ar0 + AP);
        al[1] = *(const uint32_t*)(ar1 + AP);
        al[2] = *(const uint32_t*)(ar0 + AP + 16);
        al[3] = *(const uint32_t*)(ar1 + AP + 16);
#pragma unroll
        for (int tt = 0; tt < NT; ++tt) {
            const char* bp = Bh + (tt * 8 + gid) * 48 + tig * 4;
            uint32_t bh[2], bl[2];
            bh[0] = *(const uint32_t*)(bp);
            bh[1] = *(const uint32_t*)(bp + 16);
            bl[0] = *(const uint32_t*)(bp + BP);
            bl[1] = *(const uint32_t*)(bp + BP + 16);
            mma16816(acc[tt], ah, bh);
            mma16816(acc[tt], ah, bl);
            mma16816(acc[tt], al, bh);
        }
    }

    // ---- epilogue: bias + relu, NCHW scalar stores ----
    const int p0 = R + gid, p1 = p0 + 8;
    const int yb = y << 7;
#pragma unroll
    for (int tt = 0; tt < NT; ++tt) {
        int c0 = tt * 8 + 2 * tig;
        float b0 = bias[c0], b1 = bias[c0 + 1];
        out[(size_t)c0 * NPIX + yb + p0]       = fmaxf(acc[tt][0] + b0, 0.f);
        out[(size_t)(c0 + 1) * NPIX + yb + p0] = fmaxf(acc[tt][1] + b1, 0.f);
        out[(size_t)c0 * NPIX + yb + p1]       = fmaxf(acc[tt][2] + b0, 0.f);
        out[(size_t)(c0 + 1) * NPIX + yb + p1] = fmaxf(acc[tt][3] + b1, 0.f);
    }
}

// ---------------- spatial softmax (PROVEN, reads g_buf1 NCHW) ----------------
__global__ void ssmax_kernel(int camOff)
{
    const int n = blockIdx.x;
    const int ch = blockIdx.y;
    const float* v = g_buf1 + ((size_t)n * 16 + ch) * NPIX;

    __shared__ float red[256];
    __shared__ float redx[256];
    __shared__ float redy[256];
    const int tid = threadIdx.x;

    float m = -1e30f;
    for (int p = tid; p < NPIX; p += 256) m = fmaxf(m, v[p]);
    red[tid] = m;
    __syncthreads();
    for (int s = 128; s > 0; s >>= 1) {
        if (tid < s) red[tid] = fmaxf(red[tid], red[tid + s]);
        __syncthreads();
    }
    m = red[0];
    __syncthreads();

    float s0 = 0.f, sx = 0.f, sy = 0.f;
    const float sc = 2.f / 127.f;
    for (int p = tid; p < NPIX; p += 256) {
        float e = expf(v[p] - m);
        float xx = (float)(p & 127) * sc - 1.f;
        float yy = (float)(p >> 7) * sc - 1.f;
        s0 += e;
        sx += e * xx;
        sy += e * yy;
    }
    red[tid] = s0; redx[tid] = sx; redy[tid] = sy;
    __syncthreads();
    for (int s = 128; s > 0; s >>= 1) {
        if (tid < s) {
            red[tid]  += red[tid + s];
            redx[tid] += redx[tid + s];
            redy[tid] += redy[tid + s];
        }
        __syncthreads();
    }
    if (tid == 0) {
        g_img[n * 64 + camOff + ch * 2 + 0] = redx[0] / red[0];
        g_img[n * 64 + camOff + ch * 2 + 1] = redy[0] / red[0];
    }
}

// ---------------- LSTM cell (proven) ----------------
__device__ __forceinline__ float sigf(float x) { return 1.f / (1.f + expf(-x)); }

__global__ void lstm_cell_kernel(const float* __restrict__ wih, const float* __restrict__ whh,
                                 const float* __restrict__ bih, const float* __restrict__ bhh,
                                 const float* __restrict__ states, int in_dim, int l, int t,
                                 int writeH5)
{
    __shared__ float xs[BB][576];
    __shared__ float hs[BB][HID];
    const int cur = t & 1, nxt = cur ^ 1;
    const int tid = threadIdx.x;
    const int imoff = in_dim - 64;

    for (int e = tid; e < BB * in_dim; e += blockDim.x) {
        int b = e / in_dim, k = e - b * in_dim;
        float v;
        if (k >= imoff)      v = g_img[(b * TT + t) * 64 + (k - imoff)];
        else if (l == 0)     v = states[(b * TT + t) * 6 + k];
        else                 v = g_h[nxt][l - 1][b][k];
        xs[b][k] = v;
    }
    for (int e = tid; e < BB * HID; e += blockDim.x) {
        int b = e >> 9, k = e & 511;
        hs[b][k] = g_h[cur][l][b][k];
    }
    __syncthreads();

    const int warp = tid >> 5, lane = tid & 31;
    const int u = blockIdx.x * (blockDim.x >> 5) + warp;

    float acc[4][4];
#pragma unroll
    for (int g = 0; g < 4; ++g)
#pragma unroll
        for (int b = 0; b < 4; ++b) acc[g][b] = 0.f;

    for (int k = lane; k < in_dim; k += 32) {
        float x0 = xs[0][k], x1 = xs[1][k], x2 = xs[2][k], x3 = xs[3][k];
#pragma unroll
        for (int g = 0; g < 4; ++g) {
            float w = wih[(u + g * HID) * in_dim + k];
            acc[g][0] += w * x0; acc[g][1] += w * x1;
            acc[g][2] += w * x2; acc[g][3] += w * x3;
        }
    }
    for (int k = lane; k < HID; k += 32) {
        float h0 = hs[0][k], h1 = hs[1][k], h2 = hs[2][k], h3 = hs[3][k];
#pragma unroll
        for (int g = 0; g < 4; ++g) {
            float w = whh[(u + g * HID) * HID + k];
            acc[g][0] += w * h0; acc[g][1] += w * h1;
            acc[g][2] += w * h2; acc[g][3] += w * h3;
        }
    }
#pragma unroll
    for (int off = 16; off; off >>= 1)
#pragma unroll
        for (int g = 0; g < 4; ++g)
#pragma unroll
            for (int b = 0; b < 4; ++b)
                acc[g][b] += __shfl_down_sync(0xffffffffu, acc[g][b], off);

    if (lane == 0) {
        float bi = bih[u]           + bhh[u];
        float bf = bih[u + HID]     + bhh[u + HID];
        float bg = bih[u + 2 * HID] + bhh[u + 2 * HID];
        float bo = bih[u + 3 * HID] + bhh[u + 3 * HID];
#pragma unroll
        for (int b = 0; b < 4; ++b) {
            float gi = sigf(acc[0][b] + bi);
            float gf = sigf(acc[1][b] + bf);
            float gg = tanhf(acc[2][b] + bg);
            float go = sigf(acc[3][b] + bo);
            float c2 = gf * g_c[cur][l][b][u] + gi * gg;
            float h2 = go * tanhf(c2);
            g_c[nxt][l][b][u] = c2;
            g_h[nxt][l][b][u] = h2;
            if (writeH5) g_h5[t][b][u] = h2;
        }
    }
}

// ---------------- final linear head (proven) ----------------
__global__ void outproj_kernel(const float* __restrict__ out_w, const float* __restrict__ out_b,
                               float* __restrict__ out)
{
    const int bt = blockIdx.x;
    const int b = bt / TT, t = bt - b * TT;
    const int warp = threadIdx.x >> 5, lane = threadIdx.x & 31;
    if (warp >= 6) return;
    float acc = 0.f;
    for (int k = lane; k < 576; k += 32) {
        float xv = (k < HID) ? g_h5[t][b][k] : g_img[(b * TT + t) * 64 + (k - HID)];
        acc += xv * out_w[warp * 576 + k];
    }
#pragma unroll
    for (int off = 16; off; off >>= 1) acc += __shfl_down_sync(0xffffffffu, acc, off);
    if (lane == 0) out[(b * TT + t) * 6 + warp] = acc + out_b[warp];
}

// ---------------- launcher ----------------
extern "C" void kernel_launch(void* const* d_in, const int* in_sizes, int n_in,
                              void* d_out, int out_size)
{
    const float* img_m  = (const float*)d_in[0];
    const float* img_s  = (const float*)d_in[1];
    const float* states = (const float*)d_in[2];

    const float* w[2][4];
    const float* bw[2][4];
    for (int c = 0; c < 2; ++c)
        for (int j = 0; j < 4; ++j) {
            w[c][j]  = (const float*)d_in[3 + c * 8 + j * 2];
            bw[c][j] = (const float*)d_in[3 + c * 8 + j * 2 + 1];
        }

    const float* wih0  = (const float*)d_in[19];
    const float* whh0  = (const float*)d_in[20];
    const float* bih0  = (const float*)d_in[21];
    const float* bhh0  = (const float*)d_in[22];
    const float* wih_r = (const float*)d_in[23];
    const float* whh_r = (const float*)d_in[24];
    const float* bih_r = (const float*)d_in[25];
    const float* bhh_r = (const float*)d_in[26];
    const float* out_w = (const float*)d_in[27];
    const float* out_b = (const float*)d_in[28];
    float* out = (float*)d_out;

    // dynamic smem: 2*6144 (A) + 2*OC*48 (B)
    const int SM1 = 12288 + 2 * 64 * 48;    // 18432
    const int SM2 = 12288 + 2 * 128 * 48;   // 24576
    const int SM3 = 12288 + 2 * 16 * 48;    // 13824

    zero_state_kernel<<<48, 256>>>();

    for (int c = 0; c < 2; ++c) {
        const float* im = c ? img_s : img_m;
        // layer0 (proven R2): ext -> buf0 NCHW
        conv_kernel<32, 2><<<dim3(256, 1, NIMG), 256>>>(im, 0, w[c][0], bw[c][0], 3, 32);
        // layers 1-3: tensor-core conv, NCHW ping-pong
        convmma2_kernel<32, 64><<<dim3(128, NIMG), 256, SM1>>>(0, 1, w[c][1], bw[c][1]);
        convmma2_kernel<64, 128><<<dim3(128, NIMG), 256, SM2>>>(1, 0, w[c][2], bw[c][2]);
        convmma2_kernel<128, 16><<<dim3(128, NIMG), 256, SM3>>>(0, 1, w[c][3], bw[c][3]);
        // proven ssmax reads buf1
        ssmax_kernel<<<dim3(NIMG, 16), 256>>>(c * 32);
    }

    for (int t = 0; t < TT; ++t) {
        lstm_cell_kernel<<<128, 128>>>(wih0, whh0, bih0, bhh0, states, 70, 0, t, 0);
        for (int l = 1; l < NL; ++l) {
            lstm_cell_kernel<<<128, 128>>>(wih_r + (size_t)(l - 1) * 2048 * 576,
                                           whh_r + (size_t)(l - 1) * 2048 * 512,
                                           bih_r + (l - 1) * 2048,
                                           bhh_r + (l - 1) * 2048,
                                           nullptr, 576, l, t, (l == NL - 1) ? 1 : 0);
        }
    }
    outproj_kernel<<<40, 192>>>(out_w, out_b, out);
}

// round 16
// speedup vs baseline: 2.1362x; 1.1423x over previous
#include <cuda_runtime.h>
#include <cuda_fp16.h>
#include <cstdint>

#define IMGD 128
#define NPIX (IMGD*IMGD)
#define NIMG 40
#define TT 10
#define BB 4
#define HID 512
#define NL 6

// ---------------- scratch (static device globals; no allocation) ----------------
__device__ float g_buf0[(size_t)NIMG * 128 * NPIX];   // NCHW ping
__device__ float g_buf1[(size_t)NIMG * 128 * NPIX];   // NCHW pong
__device__ float g_img[BB * TT * 64];
__device__ float g_h[2][NL][BB][HID];
__device__ float g_c[2][NL][BB][HID];
__device__ float g_h5[TT][BB][HID];

// ---------------- helpers ----------------
__device__ __forceinline__ void mma16816(float* d, const uint32_t* a, const uint32_t* b) {
    asm volatile("mma.sync.aligned.m16n8k16.row.col.f32.f16.f16.f32 "
                 "{%0,%1,%2,%3}, {%4,%5,%6,%7}, {%8,%9}, {%0,%1,%2,%3};"
                 : "+f"(d[0]), "+f"(d[1]), "+f"(d[2]), "+f"(d[3])
                 : "r"(a[0]), "r"(a[1]), "r"(a[2]), "r"(a[3]), "r"(b[0]), "r"(b[1]));
}

// ---------------- zero initial LSTM state ----------------
__global__ void zero_state_kernel()
{
    int tid = blockIdx.x * blockDim.x + threadIdx.x;
    const int total = NL * BB * HID;
    if (tid < total) {
        ((float*)g_h)[tid] = 0.f;
        ((float*)g_c)[tid] = 0.f;
    }
}

// ---------------- layer0 (K=27): PROVEN R2 implicit-GEMM kernel, NCHW ----------------
template<int BM, int TM>
__global__ void conv_kernel(const float* __restrict__ ext_in, int out_sel,
                            const float* __restrict__ wt, const float* __restrict__ bias,
                            int IC, int OC)
{
    constexpr int BN = 64, BK = 16, TN = 4;
    constexpr int AST = BM + 4, BST = BN + 4;
    __shared__ __align__(16) float As[BK * AST];
    __shared__ __align__(16) float Bs[BK * BST];

    float* outb = (out_sel == 0) ? g_buf0 : g_buf1;

    const int n = blockIdx.z;
    const float* in = ext_in + (size_t)n * IC * NPIX;
    float* out = outb + (size_t)n * OC * NPIX;

    const int p0  = blockIdx.x * BN;
    const int oc0 = blockIdx.y * BM;
    const int py  = p0 >> 7;
    const int x0  = p0 & 127;
    const int K   = IC * 9;

    const int tid = threadIdx.x;
    const int tx = tid & 15, ty = tid >> 4;

    float acc[TM][TN];
#pragma unroll
    for (int r = 0; r < TM; ++r)
#pragma unroll
        for (int c = 0; c < TN; ++c) acc[r][c] = 0.f;

    for (int k0 = 0; k0 < K; k0 += BK) {
#pragma unroll
        for (int e = tid; e < BM * BK; e += 256) {
            int j = e & (BK - 1);
            int i = e >> 4;
            int k = k0 + j, oc = oc0 + i;
            float v = 0.f;
            if (k < K && oc < OC) v = wt[oc * K + k];
            As[j * AST + i] = v;
        }
#pragma unroll
        for (int e = tid; e < BK * BN; e += 256) {
            int j  = e >> 6;
            int pp = e & 63;
            int k = k0 + j;
            float v = 0.f;
            if (k < K) {
                int ic = k / 9;
                int r  = k - ic * 9;
                int ky = r / 3;
                int kx = r - ky * 3;
                int iy = py + ky - 1;
                int ix = x0 + pp + kx - 1;
                if ((unsigned)iy < 128u && (unsigned)ix < 128u)
                    v = in[ic * NPIX + iy * IMGD + ix];
            }
            Bs[j * BST + pp] = v;
        }
        __syncthreads();

#pragma unroll
        for (int j = 0; j < BK; ++j) {
            float bv[TN];
            float4 b4 = *(const float4*)&Bs[j * BST + tx * TN];
            bv[0] = b4.x; bv[1] = b4.y; bv[2] = b4.z; bv[3] = b4.w;
            float av[TM];
#pragma unroll
            for (int r = 0; r < TM; ++r) av[r] = As[j * AST + ty * TM + r];
#pragma unroll
            for (int r = 0; r < TM; ++r)
#pragma unroll
                for (int c = 0; c < TN; ++c)
                    acc[r][c] = fmaf(av[r], bv[c], acc[r][c]);
        }
        __syncthreads();
    }

#pragma unroll
    for (int r = 0; r < TM; ++r) {
        int oc = oc0 + ty * TM + r;
        if (oc < OC) {
            float bsv = bias[oc];
            float4 o;
            o.x = fmaxf(acc[r][0] + bsv, 0.f);
            o.y = fmaxf(acc[r][1] + bsv, 0.f);
            o.z = fmaxf(acc[r][2] + bsv, 0.f);
            o.w = fmaxf(acc[r][3] + bsv, 0.f);
            *(float4*)&out[oc * NPIX + p0 + tx * TN] = o;
        }
    }
}

// ---------------- layers 1-3: fp16-split mma conv, pipelined staging ----------------
// block = (row y, image n), 256 threads. Same verified index math as R14,
// plus: register prefetch of next K-chunk + ping-pong smem + 1 sync/chunk.
template<int IC, int OC>
__global__ void __launch_bounds__(256)
convmma3_kernel(int in_sel, int out_sel,
                const float* __restrict__ wt, const float* __restrict__ bias)
{
    constexpr int K  = IC * 9;
    constexpr int NT = OC / 8;            // n8 tiles
    constexpr int NB = OC / 16;           // B floats per thread per chunk
    constexpr int AP = 128 * 48;          // A plane bytes
    constexpr int BP = OC * 48;           // B plane bytes
    constexpr int CB = 2 * AP + 2 * BP;   // bytes per chunk buffer

    extern __shared__ __align__(16) char sm[];

    const float* inb = (in_sel == 0) ? g_buf0 : g_buf1;
    float* outb = (out_sel == 0) ? g_buf0 : g_buf1;
    const int n = blockIdx.y, y = blockIdx.x;
    const float* in = inb + (size_t)n * IC * NPIX;
    float* out = outb + (size_t)n * OC * NPIX;

    const int tid = threadIdx.x, lane = tid & 31, wid = tid >> 5;
    const int tig = lane & 3, gid = lane >> 2;
    const int R = wid * 16;
    const int pA = tid & 127;       // pixel for A staging
    const int jh = tid >> 7;        // 0/1: which j of the pair

    float aReg[8];
    float bReg[NB];

    auto loadA = [&](int k0) {
#pragma unroll
        for (int q = 0; q < 8; ++q) {
            int j = q * 2 + jh;
            int k = k0 + j;
            int ic = k / 9;
            int r  = k - ic * 9;
            int ky = r / 3;
            int kx = r - ky * 3;
            int iy = y + ky - 1;
            int ix = pA + kx - 1;
            aReg[q] = ((unsigned)iy < 128u && (unsigned)ix < 128u)
                        ? in[ic * NPIX + iy * IMGD + ix] : 0.f;
        }
    };
    auto loadB = [&](int k0) {
#pragma unroll
        for (int i = 0; i < NB; ++i) {
            int idx = tid + i * 256;
            int oc = idx >> 4, j = idx & 15;
            bReg[i] = wt[(size_t)oc * K + k0 + j];
        }
    };
    auto storeAB = [&](char* base) {
        char* Ah = base;
        char* Al = base + AP;
        char* Bh = base + 2 * AP;
        char* Bl = Bh + BP;
#pragma unroll
        for (int q = 0; q < 8; ++q) {
            int j = q * 2 + jh;
            __half h = __float2half_rn(aReg[q]);
            __half l = __float2half_rn(aReg[q] - __half2float(h));
            *(unsigned short*)(Ah + pA * 48 + j * 2) = __half_as_ushort(h);
            *(unsigned short*)(Al + pA * 48 + j * 2) = __half_as_ushort(l);
        }
#pragma unroll
        for (int i = 0; i < NB; ++i) {
            int idx = tid + i * 256;
            int oc = idx >> 4, j = idx & 15;
            __half h = __float2half_rn(bReg[i]);
            __half l = __float2half_rn(bReg[i] - __half2float(h));
            *(unsigned short*)(Bh + oc * 48 + j * 2) = __half_as_ushort(h);
            *(unsigned short*)(Bl + oc * 48 + j * 2) = __half_as_ushort(l);
        }
    };

    float acc[NT][4];
#pragma unroll
    for (int t = 0; t < NT; ++t)
#pragma unroll
        for (int i = 0; i < 4; ++i) acc[t][i] = 0.f;

    loadA(0);
    loadB(0);

    for (int k0 = 0; k0 < K; k0 += 16) {
        char* base = sm + ((k0 >> 4) & 1) * CB;
        storeAB(base);
        __syncthreads();
        if (k0 + 16 < K) {              // prefetch next chunk (overlaps compute)
            loadA(k0 + 16);
            loadB(k0 + 16);
        }
        // ---- fragments (PTX ISA tables) + mma ----
        const char* Ah = base;
        const char* Bh = base + 2 * AP;
        const char* ar0 = Ah + (R + gid) * 48 + tig * 4;
        const char* ar1 = ar0 + 8 * 48;
        uint32_t ah[4], al[4];
        ah[0] = *(const uint32_t*)(ar0);
        ah[1] = *(const uint32_t*)(ar1);
        ah[2] = *(const uint32_t*)(ar0 + 16);
        ah[3] = *(const uint32_t*)(ar1 + 16);
        al[0] = *(const uint32_t*)(ar0 + AP);
        al[1] = *(const uint32_t*)(ar1 + AP);
        al[2] = *(const uint32_t*)(ar0 + AP + 16);
        al[3] = *(const uint32_t*)(ar1 + AP + 16);
#pragma unroll
        for (int tt = 0; tt < NT; ++tt) {
            const char* bp = Bh + (tt * 8 + gid) * 48 + tig * 4;
            uint32_t bh[2], bl[2];
            bh[0] = *(const uint32_t*)(bp);
            bh[1] = *(const uint32_t*)(bp + 16);
            bl[0] = *(const uint32_t*)(bp + BP);
            bl[1] = *(const uint32_t*)(bp + BP + 16);
            mma16816(acc[tt], ah, bh);
            mma16816(acc[tt], ah, bl);
            mma16816(acc[tt], al, bh);
        }
    }

    // ---- epilogue: bias + relu, NCHW scalar stores ----
    const int p0 = R + gid, p1 = p0 + 8;
    const int yb = y << 7;
#pragma unroll
    for (int tt = 0; tt < NT; ++tt) {
        int c0 = tt * 8 + 2 * tig;
        float b0 = bias[c0], b1 = bias[c0 + 1];
        out[(size_t)c0 * NPIX + yb + p0]       = fmaxf(acc[tt][0] + b0, 0.f);
        out[(size_t)(c0 + 1) * NPIX + yb + p0] = fmaxf(acc[tt][1] + b1, 0.f);
        out[(size_t)c0 * NPIX + yb + p1]       = fmaxf(acc[tt][2] + b0, 0.f);
        out[(size_t)(c0 + 1) * NPIX + yb + p1] = fmaxf(acc[tt][3] + b1, 0.f);
    }
}

// ---------------- spatial softmax (PROVEN, reads g_buf1 NCHW) ----------------
__global__ void ssmax_kernel(int camOff)
{
    const int n = blockIdx.x;
    const int ch = blockIdx.y;
    const float* v = g_buf1 + ((size_t)n * 16 + ch) * NPIX;

    __shared__ float red[256];
    __shared__ float redx[256];
    __shared__ float redy[256];
    const int tid = threadIdx.x;

    float m = -1e30f;
    for (int p = tid; p < NPIX; p += 256) m = fmaxf(m, v[p]);
    red[tid] = m;
    __syncthreads();
    for (int s = 128; s > 0; s >>= 1) {
        if (tid < s) red[tid] = fmaxf(red[tid], red[tid + s]);
        __syncthreads();
    }
    m = red[0];
    __syncthreads();

    float s0 = 0.f, sx = 0.f, sy = 0.f;
    const float sc = 2.f / 127.f;
    for (int p = tid; p < NPIX; p += 256) {
        float e = expf(v[p] - m);
        float xx = (float)(p & 127) * sc - 1.f;
        float yy = (float)(p >> 7) * sc - 1.f;
        s0 += e;
        sx += e * xx;
        sy += e * yy;
    }
    red[tid] = s0; redx[tid] = sx; redy[tid] = sy;
    __syncthreads();
    for (int s = 128; s > 0; s >>= 1) {
        if (tid < s) {
            red[tid]  += red[tid + s];
            redx[tid] += redx[tid + s];
            redy[tid] += redy[tid + s];
        }
        __syncthreads();
    }
    if (tid == 0) {
        g_img[n * 64 + camOff + ch * 2 + 0] = redx[0] / red[0];
        g_img[n * 64 + camOff + ch * 2 + 1] = redy[0] / red[0];
    }
}

// ---------------- LSTM cell (proven) ----------------
__device__ __forceinline__ float sigf(float x) { return 1.f / (1.f + expf(-x)); }

__global__ void lstm_cell_kernel(const float* __restrict__ wih, const float* __restrict__ whh,
                                 const float* __restrict__ bih, const float* __restrict__ bhh,
                                 const float* __restrict__ states, int in_dim, int l, int t,
                                 int writeH5)
{
    __shared__ float xs[BB][576];
    __shared__ float hs[BB][HID];
    const int cur = t & 1, nxt = cur ^ 1;
    const int tid = threadIdx.x;
    const int imoff = in_dim - 64;

    for (int e = tid; e < BB * in_dim; e += blockDim.x) {
        int b = e / in_dim, k = e - b * in_dim;
        float v;
        if (k >= imoff)      v = g_img[(b * TT + t) * 64 + (k - imoff)];
        else if (l == 0)     v = states[(b * TT + t) * 6 + k];
        else                 v = g_h[nxt][l - 1][b][k];
        xs[b][k] = v;
    }
    for (int e = tid; e < BB * HID; e += blockDim.x) {
        int b = e >> 9, k = e & 511;
        hs[b][k] = g_h[cur][l][b][k];
    }
    __syncthreads();

    const int warp = tid >> 5, lane = tid & 31;
    const int u = blockIdx.x * (blockDim.x >> 5) + warp;

    float acc[4][4];
#pragma unroll
    for (int g = 0; g < 4; ++g)
#pragma unroll
        for (int b = 0; b < 4; ++b) acc[g][b] = 0.f;

    for (int k = lane; k < in_dim; k += 32) {
        float x0 = xs[0][k], x1 = xs[1][k], x2 = xs[2][k], x3 = xs[3][k];
#pragma unroll
        for (int g = 0; g < 4; ++g) {
            float w = wih[(u + g * HID) * in_dim + k];
            acc[g][0] += w * x0; acc[g][1] += w * x1;
            acc[g][2] += w * x2; acc[g][3] += w * x3;
        }
    }
    for (int k = lane; k < HID; k += 32) {
        float h0 = hs[0][k], h1 = hs[1][k], h2 = hs[2][k], h3 = hs[3][k];
#pragma unroll
        for (int g = 0; g < 4; ++g) {
            float w = whh[(u + g * HID) * HID + k];
            acc[g][0] += w * h0; acc[g][1] += w * h1;
            acc[g][2] += w * h2; acc[g][3] += w * h3;
        }
    }
#pragma unroll
    for (int off = 16; off; off >>= 1)
#pragma unroll
        for (int g = 0; g < 4; ++g)
#pragma unroll
            for (int b = 0; b < 4; ++b)
                acc[g][b] += __shfl_down_sync(0xffffffffu, acc[g][b], off);

    if (lane == 0) {
        float bi = bih[u]           + bhh[u];
        float bf = bih[u + HID]     + bhh[u + HID];
        float bg = bih[u + 2 * HID] + bhh[u + 2 * HID];
        float bo = bih[u + 3 * HID] + bhh[u + 3 * HID];
#pragma unroll
        for (int b = 0; b < 4; ++b) {
            float gi = sigf(acc[0][b] + bi);
            float gf = sigf(acc[1][b] + bf);
            float gg = tanhf(acc[2][b] + bg);
            float go = sigf(acc[3][b] + bo);
            float c2 = gf * g_c[cur][l][b][u] + gi * gg;
            float h2 = go * tanhf(c2);
            g_c[nxt][l][b][u] = c2;
            g_h[nxt][l][b][u] = h2;
            if (writeH5) g_h5[t][b][u] = h2;
        }
    }
}

// ---------------- final linear head (proven) ----------------
__global__ void outproj_kernel(const float* __restrict__ out_w, const float* __restrict__ out_b,
                               float* __restrict__ out)
{
    const int bt = blockIdx.x;
    const int b = bt / TT, t = bt - b * TT;
    const int warp = threadIdx.x >> 5, lane = threadIdx.x & 31;
    if (warp >= 6) return;
    float acc = 0.f;
    for (int k = lane; k < 576; k += 32) {
        float xv = (k < HID) ? g_h5[t][b][k] : g_img[(b * TT + t) * 64 + (k - HID)];
        acc += xv * out_w[warp * 576 + k];
    }
#pragma unroll
    for (int off = 16; off; off >>= 1) acc += __shfl_down_sync(0xffffffffu, acc, off);
    if (lane == 0) out[(b * TT + t) * 6 + warp] = acc + out_b[warp];
}

// ---------------- launcher ----------------
extern "C" void kernel_launch(void* const* d_in, const int* in_sizes, int n_in,
                              void* d_out, int out_size)
{
    const float* img_m  = (const float*)d_in[0];
    const float* img_s  = (const float*)d_in[1];
    const float* states = (const float*)d_in[2];

    const float* w[2][4];
    const float* bw[2][4];
    for (int c = 0; c < 2; ++c)
        for (int j = 0; j < 4; ++j) {
            w[c][j]  = (const float*)d_in[3 + c * 8 + j * 2];
            bw[c][j] = (const float*)d_in[3 + c * 8 + j * 2 + 1];
        }

    const float* wih0  = (const float*)d_in[19];
    const float* whh0  = (const float*)d_in[20];
    const float* bih0  = (const float*)d_in[21];
    const float* bhh0  = (const float*)d_in[22];
    const float* wih_r = (const float*)d_in[23];
    const float* whh_r = (const float*)d_in[24];
    const float* bih_r = (const float*)d_in[25];
    const float* bhh_r = (const float*)d_in[26];
    const float* out_w = (const float*)d_in[27];
    const float* out_b = (const float*)d_in[28];
    float* out = (float*)d_out;

    // dynamic smem: 2 chunk buffers x (2*6144 A + 2*OC*48 B)
    const int SM1 = 2 * (12288 + 2 * 64 * 48);    // 36864
    const int SM2 = 2 * (12288 + 2 * 128 * 48);   // 49152
    const int SM3 = 2 * (12288 + 2 * 16 * 48);    // 27648
    static bool attr_done = false;
    if (!attr_done) {
        cudaFuncSetAttribute(convmma3_kernel<32, 64>,  cudaFuncAttributeMaxDynamicSharedMemorySize, SM1);
        cudaFuncSetAttribute(convmma3_kernel<64, 128>, cudaFuncAttributeMaxDynamicSharedMemorySize, SM2);
        cudaFuncSetAttribute(convmma3_kernel<128, 16>, cudaFuncAttributeMaxDynamicSharedMemorySize, SM3);
        attr_done = true;
    }

    zero_state_kernel<<<48, 256>>>();

    for (int c = 0; c < 2; ++c) {
        const float* im = c ? img_s : img_m;
        // layer0 (proven R2): ext -> buf0 NCHW
        conv_kernel<32, 2><<<dim3(256, 1, NIMG), 256>>>(im, 0, w[c][0], bw[c][0], 3, 32);
        // layers 1-3: pipelined tensor-core conv, NCHW ping-pong
        convmma3_kernel<32, 64><<<dim3(128, NIMG), 256, SM1>>>(0, 1, w[c][1], bw[c][1]);
        convmma3_kernel<64, 128><<<dim3(128, NIMG), 256, SM2>>>(1, 0, w[c][2], bw[c][2]);
        convmma3_kernel<128, 16><<<dim3(128, NIMG), 256, SM3>>>(0, 1, w[c][3], bw[c][3]);
        // proven ssmax reads buf1
        ssmax_kernel<<<dim3(NIMG, 16), 256>>>(c * 32);
    }

    for (int t = 0; t < TT; ++t) {
        lstm_cell_kernel<<<128, 128>>>(wih0, whh0, bih0, bhh0, states, 70, 0, t, 0);
        for (int l = 1; l < NL; ++l) {
            lstm_cell_kernel<<<128, 128>>>(wih_r + (size_t)(l - 1) * 2048 * 576,
                                           whh_r + (size_t)(l - 1) * 2048 * 512,
                                           bih_r + (l - 1) * 2048,
                                           bhh_r + (l - 1) * 2048,
                                           nullptr, 576, l, t, (l == NL - 1) ? 1 : 0);
        }
    }
    outproj_kernel<<<40, 192>>>(out_w, out_b, out);
}